// round 1
// baseline (speedup 1.0000x reference)
#include <cuda_runtime.h>
#include <math.h>

// ---------------------------------------------------------------------------
// Problem constants
// ---------------------------------------------------------------------------
#define BB    4          // batch
#define SEQ   3072       // tokens (48*64)
#define DIMC  768        // model dim
#define NH    3          // heads
#define HDIM  256        // head dim
#define DD    262        // head dim + 6 positional
#define BHN   12         // BB*NH
#define HD3   786        // NH*DD

// ---------------------------------------------------------------------------
// Scratch (device globals: the sanctioned alloc-free scratch mechanism)
// ---------------------------------------------------------------------------
static __device__ float g_qkvP[(size_t)3 * BHN * SEQ * HDIM];   // 113 MB  [s][bh][n][d]
static __device__ float g_attn[(size_t)BHN * SEQ * SEQ];        // 453 MB  [bh][n][m]
static __device__ float g_vcat[(size_t)BHN * SEQ * DD];         // 38.6 MB [bh][n][e]
static __device__ float g_f1  [(size_t)BHN * DD * SEQ];         // 38.6 MB [bh][d][m]
static __device__ float g_fund[(size_t)BHN * DD * DD];          // 3.3 MB  [bh][d][e]
static __device__ float g_fundT[(size_t)BB * DD * HD3];         // 3.3 MB  [b][e][h*DD+d]
static __device__ float g_rmax[BHN * SEQ];
static __device__ float g_rinv[BHN * SEQ];
static __device__ float g_cmax[BHN * SEQ];
static __device__ float g_cinv[BHN * SEQ];

// ---------------------------------------------------------------------------
// Generic 128x128x16 tiled fp32 GEMM, 256 threads, 8x8 register tile.
//   C[i,j] = alpha * sum_k A(i,k) * B(j,k)   (+ epilogue variants)
// AMODE 0: A[i*lda + k]  (k contiguous)     AMODE 1: A[k*lda + i] (i contiguous)
// BMODE 0: B[j*ldb + k]  (k contiguous)     BMODE 1: B[k*ldb + j] (j contiguous)
// EPI 0: plain store; EPI 1: QKV scatter to g_qkvP layout; EPI 2: += bias[j]
// ---------------------------------------------------------------------------
template<int AMODE, int BMODE, int EPI>
__global__ void __launch_bounds__(256, 2) gemm_k(
    const float* __restrict__ A, const float* __restrict__ B,
    float* __restrict__ C, const float* __restrict__ bias,
    int M, int N, int K, int lda, int ldb, int ldc,
    long long sA, long long sB, long long sC, float alpha)
{
    A += (long long)blockIdx.z * sA;
    B += (long long)blockIdx.z * sB;
    C += (long long)blockIdx.z * sC;
    const int i0 = blockIdx.y * 128;
    const int j0 = blockIdx.x * 128;

    __shared__ float As[16][128];
    __shared__ float Bs[16][128];

    float acc[8][8];
#pragma unroll
    for (int r = 0; r < 8; r++)
#pragma unroll
        for (int c = 0; c < 8; c++) acc[r][c] = 0.f;

    const int tid = threadIdx.x;
    const int tx = tid & 15;
    const int ty = tid >> 4;

    for (int k0 = 0; k0 < K; k0 += 16) {
        // ---- A tile -> As[k][i]
        if (AMODE == 0) {
#pragma unroll
            for (int rep = 0; rep < 2; rep++) {
                int t  = tid + rep * 256;
                int i  = t >> 2;
                int kg = (t & 3) * 4;
                int gi = i0 + i;
                const float* ap = A + (long long)gi * lda + k0 + kg;
                bool iok = gi < M;
#pragma unroll
                for (int c = 0; c < 4; c++) {
                    int gk = k0 + kg + c;
                    As[kg + c][i] = (iok && gk < K) ? ap[c] : 0.f;
                }
            }
        } else {
#pragma unroll
            for (int rep = 0; rep < 2; rep++) {
                int t  = tid + rep * 256;
                int k  = t >> 5;
                int ig = (t & 31) * 4;
                int gk = k0 + k;
                const float* ap = A + (long long)gk * lda + i0 + ig;
                bool kok = gk < K;
#pragma unroll
                for (int c = 0; c < 4; c++) {
                    int gi = i0 + ig + c;
                    As[k][ig + c] = (kok && gi < M) ? ap[c] : 0.f;
                }
            }
        }
        // ---- B tile -> Bs[k][j]
        if (BMODE == 0) {
#pragma unroll
            for (int rep = 0; rep < 2; rep++) {
                int t  = tid + rep * 256;
                int j  = t >> 2;
                int kg = (t & 3) * 4;
                int gj = j0 + j;
                const float* bp = B + (long long)gj * ldb + k0 + kg;
                bool jok = gj < N;
#pragma unroll
                for (int c = 0; c < 4; c++) {
                    int gk = k0 + kg + c;
                    Bs[kg + c][j] = (jok && gk < K) ? bp[c] : 0.f;
                }
            }
        } else {
#pragma unroll
            for (int rep = 0; rep < 2; rep++) {
                int t  = tid + rep * 256;
                int k  = t >> 5;
                int jg = (t & 31) * 4;
                int gk = k0 + k;
                const float* bp = B + (long long)gk * ldb + j0 + jg;
                bool kok = gk < K;
#pragma unroll
                for (int c = 0; c < 4; c++) {
                    int gj = j0 + jg + c;
                    Bs[k][jg + c] = (kok && gj < N) ? bp[c] : 0.f;
                }
            }
        }
        __syncthreads();

#pragma unroll
        for (int kk = 0; kk < 16; kk++) {
            float a[8], b[8];
#pragma unroll
            for (int r = 0; r < 8; r++) a[r] = As[kk][ty * 8 + r];
#pragma unroll
            for (int c = 0; c < 8; c++) b[c] = Bs[kk][tx * 8 + c];
#pragma unroll
            for (int r = 0; r < 8; r++)
#pragma unroll
                for (int c = 0; c < 8; c++)
                    acc[r][c] = fmaf(a[r], b[c], acc[r][c]);
        }
        __syncthreads();
    }

    // ---- epilogue
#pragma unroll
    for (int r = 0; r < 8; r++) {
        int gi = i0 + ty * 8 + r;
        if (gi >= M) continue;
#pragma unroll
        for (int c = 0; c < 8; c++) {
            int gj = j0 + tx * 8 + c;
            if (gj >= N) continue;
            float v = acc[r][c] * alpha;
            if (EPI == 2) v += bias[gj];
            if (EPI == 1) {
                // scatter qkv column j=(s,h,d), row i=(b,n) -> g_qkvP[s][b*NH+h][n][d]
                int s  = gj / DIMC;
                int rc = gj - s * DIMC;
                int h  = rc >> 8;
                int d  = rc & 255;
                int b_ = gi / SEQ;
                int n  = gi - b_ * SEQ;
                long long dst = ((((long long)s * BHN) + (b_ * NH + h)) * SEQ + n) * HDIM + d;
                C[dst] = v;
            } else {
                C[(long long)gi * ldc + gj] = v;
            }
        }
    }
}

// ---------------------------------------------------------------------------
// Row softmax stats: per attn row -> max and 1/sum(exp(a-max))
// ---------------------------------------------------------------------------
__global__ void row_stats(const float* __restrict__ attn,
                          float* __restrict__ rmax, float* __restrict__ rinv)
{
    __shared__ float sm[128];
    const long long row = blockIdx.x;
    const float* a = attn + row * SEQ;
    const int t = threadIdx.x;

    float m = -INFINITY;
    for (int i = t; i < SEQ; i += 128) m = fmaxf(m, a[i]);
    sm[t] = m; __syncthreads();
    for (int off = 64; off > 0; off >>= 1) {
        if (t < off) sm[t] = fmaxf(sm[t], sm[t + off]);
        __syncthreads();
    }
    const float M = sm[0]; __syncthreads();

    float s = 0.f;
    for (int i = t; i < SEQ; i += 128) s += __expf(a[i] - M);
    sm[t] = s; __syncthreads();
    for (int off = 64; off > 0; off >>= 1) {
        if (t < off) sm[t] += sm[t + off];
        __syncthreads();
    }
    if (t == 0) { rmax[row] = M; rinv[row] = 1.f / sm[0]; }
}

// ---------------------------------------------------------------------------
// Column softmax stats: online max/sum per column, single pass over attn
// ---------------------------------------------------------------------------
__global__ void col_stats(const float* __restrict__ attn,
                          float* __restrict__ cmax, float* __restrict__ cinv)
{
    const int bh = blockIdx.y;
    const int m  = blockIdx.x * 128 + threadIdx.x;
    const float* a = attn + (long long)bh * SEQ * SEQ + m;

    float mx[4] = {-INFINITY, -INFINITY, -INFINITY, -INFINITY};
    float ss[4] = {0.f, 0.f, 0.f, 0.f};
    for (int n = 0; n < SEQ; n += 4) {
#pragma unroll
        for (int u = 0; u < 4; u++) {
            float v = a[(long long)(n + u) * SEQ];
            if (v <= mx[u]) {
                ss[u] += __expf(v - mx[u]);
            } else {
                ss[u] = ss[u] * __expf(mx[u] - v) + 1.f;
                mx[u] = v;
            }
        }
    }
    float M = fmaxf(fmaxf(mx[0], mx[1]), fmaxf(mx[2], mx[3]));
    float S = 0.f;
#pragma unroll
    for (int u = 0; u < 4; u++) S += ss[u] * __expf(mx[u] - M);
    cmax[bh * SEQ + m] = M;
    cinv[bh * SEQ + m] = 1.f / S;
}

// ---------------------------------------------------------------------------
// attn_f = softmax_row(a) * softmax_col(a) = exp(2a - rmax - cmax)*rinv*cinv
// ---------------------------------------------------------------------------
__global__ void apply_softmax(float4* __restrict__ attn,
                              const float* __restrict__ rmax, const float* __restrict__ rinv,
                              const float* __restrict__ cmax, const float* __restrict__ cinv)
{
    const long long id = (long long)blockIdx.x * blockDim.x + threadIdx.x;  // float4 index
    if (id >= (long long)BHN * SEQ * SEQ / 4) return;
    const long long base = id * 4;
    const int m0 = (int)(base % SEQ);
    const long long rg = base / SEQ;          // global row (bh*SEQ + n)
    const int bh = (int)(rg / SEQ);

    const float rm = rmax[rg];
    const float ri = rinv[rg];
    const float4 cm = *(const float4*)(cmax + (long long)bh * SEQ + m0);
    const float4 ci = *(const float4*)(cinv + (long long)bh * SEQ + m0);

    float4 v = attn[id];
    v.x = __expf(2.f * v.x - rm - cm.x) * ri * ci.x;
    v.y = __expf(2.f * v.y - rm - cm.y) * ri * ci.y;
    v.z = __expf(2.f * v.z - rm - cm.z) * ri * ci.z;
    v.w = __expf(2.f * v.w - rm - cm.w) * ri * ci.w;
    attn[id] = v;
}

// ---------------------------------------------------------------------------
// v_cat[bh][n][0:256] = v ; [256:262] = (y^2, x^2, xy, y, x, 1)
// ---------------------------------------------------------------------------
__global__ void build_vcat(const float* __restrict__ qkvP, float* __restrict__ vcat)
{
    const int rid = blockIdx.x;          // bh*SEQ + n
    const int bh  = rid / SEQ;
    const int n   = rid - bh * SEQ;
    const float* src = qkvP + ((long long)(2 * BHN + bh) * SEQ + n) * HDIM;
    float* dst = vcat + (long long)rid * DD;
    const int t = threadIdx.x;
    dst[t] = src[t];
    if (t < 6) {
        int iy = n % 48;
        int ix = n / 48;
        float y = -1.f + 2.f * (float)iy / 47.f;
        float x = -1.f + 2.f * (float)ix / 63.f;
        float p = (t == 0) ? y * y :
                  (t == 1) ? x * x :
                  (t == 2) ? y * x :
                  (t == 3) ? y :
                  (t == 4) ? x : 1.f;
        dst[HDIM + t] = p;
    }
}

// ---------------------------------------------------------------------------
// fundT[b][e][h*DD+d] = fund[bh][d][e]   (reshape + transpose(0,2,1))
// ---------------------------------------------------------------------------
__global__ void transpose_fund(const float* __restrict__ fund, float* __restrict__ fundT)
{
    const long long idx = (long long)blockIdx.x * blockDim.x + threadIdx.x;
    if (idx >= (long long)BHN * DD * DD) return;
    const int e  = (int)(idx % DD);
    const long long r = idx / DD;
    const int d  = (int)(r % DD);
    const int bh = (int)(r / DD);
    const int b  = bh / NH;
    const int h  = bh - b * NH;
    fundT[((long long)b * DD + e) * HD3 + h * DD + d] = fund[idx];
}

// ---------------------------------------------------------------------------
// Launch
// ---------------------------------------------------------------------------
extern "C" void kernel_launch(void* const* d_in, const int* in_sizes, int n_in,
                              void* d_out, int out_size)
{
    const float* x    = (const float*)d_in[0];  // [4,3072,768]
    const float* Wqkv = (const float*)d_in[1];  // [2304,768]
    const float* Wpf  = (const float*)d_in[2];  // [768,786]
    const float* bpf  = (const float*)d_in[3];  // [768]
    float* out = (float*)d_out;                 // [4,262,768]

    float *qkvP, *attn, *vcat, *f1, *fund, *fundT, *rmax, *rinv, *cmax, *cinv;
    cudaGetSymbolAddress((void**)&qkvP,  g_qkvP);
    cudaGetSymbolAddress((void**)&attn,  g_attn);
    cudaGetSymbolAddress((void**)&vcat,  g_vcat);
    cudaGetSymbolAddress((void**)&f1,    g_f1);
    cudaGetSymbolAddress((void**)&fund,  g_fund);
    cudaGetSymbolAddress((void**)&fundT, g_fundT);
    cudaGetSymbolAddress((void**)&rmax,  g_rmax);
    cudaGetSymbolAddress((void**)&rinv,  g_rinv);
    cudaGetSymbolAddress((void**)&cmax,  g_cmax);
    cudaGetSymbolAddress((void**)&cinv,  g_cinv);

    const long long sQ = (long long)SEQ * HDIM;

    // 1) QKV projection, scattered to [s][bh][n][d]
    gemm_k<0, 0, 1><<<dim3((3 * DIMC) / 128, (BB * SEQ) / 128, 1), 256>>>(
        x, Wqkv, qkvP, nullptr,
        BB * SEQ, 3 * DIMC, DIMC, DIMC, DIMC, 0, 0, 0, 0, 1.f);

    // 2) attn = scale * q @ k^T   (batched over bh)
    gemm_k<0, 0, 0><<<dim3(SEQ / 128, SEQ / 128, BHN), 256>>>(
        qkvP, qkvP + (long long)BHN * sQ, attn, nullptr,
        SEQ, SEQ, HDIM, HDIM, HDIM, SEQ,
        sQ, sQ, (long long)SEQ * SEQ, 0.0625f);

    // 3) softmax stats
    row_stats<<<BHN * SEQ, 128>>>(attn, rmax, rinv);
    col_stats<<<dim3(SEQ / 128, BHN), 128>>>(attn, cmax, cinv);

    // 4) attn_f in place
    apply_softmax<<<(unsigned)(((long long)BHN * SEQ * SEQ / 4 + 255) / 256), 256>>>(
        (float4*)attn, rmax, rinv, cmax, cinv);

    // 5) v_cat = [v, pos]
    build_vcat<<<BHN * SEQ, 256>>>(qkvP, vcat);

    // 6) f1[d,m] = sum_n v_cat[n,d] * attn_f[n,m]
    gemm_k<1, 1, 0><<<dim3(SEQ / 128, (DD + 127) / 128, BHN), 256>>>(
        vcat, attn, f1, nullptr,
        DD, SEQ, SEQ, DD, SEQ, SEQ,
        (long long)SEQ * DD, (long long)SEQ * SEQ, (long long)DD * SEQ, 1.f);

    // 7) fund[d,e] = sum_m f1[d,m] * v_cat[m,e]
    gemm_k<0, 1, 0><<<dim3((DD + 127) / 128, (DD + 127) / 128, BHN), 256>>>(
        f1, vcat, fund, nullptr,
        DD, DD, SEQ, SEQ, DD, DD,
        (long long)DD * SEQ, (long long)SEQ * DD, (long long)DD * DD, 1.f);

    // 8) reshape/transpose
    transpose_fund<<<(int)(((long long)BHN * DD * DD + 255) / 256), 256>>>(fund, fundT);

    // 9) out[b,e,o] = sum_j fundT[b,e,j] * Wpf[o,j] + bpf[o]
    gemm_k<0, 0, 2><<<dim3(DIMC / 128, (DD + 127) / 128, BB), 256>>>(
        fundT, Wpf, out, bpf,
        DD, DIMC, HD3, HD3, HD3, DIMC,
        (long long)DD * HD3, 0, (long long)DD * DIMC, 1.f);
}

// round 2
// speedup vs baseline: 1.0024x; 1.0024x over previous
#include <cuda_runtime.h>
#include <math.h>

// ---------------------------------------------------------------------------
// Problem constants
// ---------------------------------------------------------------------------
#define BB    4          // batch
#define SEQ   3072       // tokens (48*64)
#define DIMC  768        // model dim
#define NH    3          // heads
#define HDIM  256        // head dim
#define DD    262        // head dim + 6 positional
#define BHN   12         // BB*NH
#define HD3   786        // NH*DD

// ---------------------------------------------------------------------------
// Scratch (device globals: the sanctioned alloc-free scratch mechanism)
// ---------------------------------------------------------------------------
static __device__ float g_qkvP[(size_t)3 * BHN * SEQ * HDIM];   // 113 MB  [s][bh][n][d]
static __device__ float g_attn[(size_t)BHN * SEQ * SEQ];        // 453 MB  [bh][n][m]
static __device__ float g_vcat[(size_t)BHN * SEQ * DD];         // 38.6 MB [bh][n][e]
static __device__ float g_f1  [(size_t)BHN * DD * SEQ];         // 38.6 MB [bh][d][m]
static __device__ float g_fund[(size_t)BHN * DD * DD];          // 3.3 MB  [bh][d][e]
static __device__ float g_fundT[(size_t)BB * DD * HD3];         // 3.3 MB  [b][e][h*DD+d]
static __device__ float g_rmax[BHN * SEQ];
static __device__ float g_rinv[BHN * SEQ];
static __device__ float g_cmax[BHN * SEQ];
static __device__ float g_cinv[BHN * SEQ];

// ---------------------------------------------------------------------------
// Generic 128x128x16 tiled fp32 GEMM, 256 threads, 8x8 register tile.
//   C[i,j] = alpha * sum_k A(i,k) * B(j,k)   (+ epilogue variants)
// AMODE 0: A[i*lda + k]  (k contiguous)     AMODE 1: A[k*lda + i] (i contiguous)
// BMODE 0: B[j*ldb + k]  (k contiguous)     BMODE 1: B[k*ldb + j] (j contiguous)
// EPI 0: plain store; EPI 1: QKV scatter to g_qkvP layout; EPI 2: += bias[j]
// ---------------------------------------------------------------------------
template<int AMODE, int BMODE, int EPI>
__global__ void __launch_bounds__(256, 2) gemm_k(
    const float* __restrict__ A, const float* __restrict__ B,
    float* __restrict__ C, const float* __restrict__ bias,
    int M, int N, int K, int lda, int ldb, int ldc,
    long long sA, long long sB, long long sC, float alpha)
{
    A += (long long)blockIdx.z * sA;
    B += (long long)blockIdx.z * sB;
    C += (long long)blockIdx.z * sC;
    const int i0 = blockIdx.y * 128;
    const int j0 = blockIdx.x * 128;

    __shared__ float As[16][128];
    __shared__ float Bs[16][128];

    float acc[8][8];
#pragma unroll
    for (int r = 0; r < 8; r++)
#pragma unroll
        for (int c = 0; c < 8; c++) acc[r][c] = 0.f;

    const int tid = threadIdx.x;
    const int tx = tid & 15;
    const int ty = tid >> 4;

    for (int k0 = 0; k0 < K; k0 += 16) {
        // ---- A tile -> As[k][i]
        if (AMODE == 0) {
#pragma unroll
            for (int rep = 0; rep < 2; rep++) {
                int t  = tid + rep * 256;
                int i  = t >> 2;
                int kg = (t & 3) * 4;
                int gi = i0 + i;
                const float* ap = A + (long long)gi * lda + k0 + kg;
                bool iok = gi < M;
#pragma unroll
                for (int c = 0; c < 4; c++) {
                    int gk = k0 + kg + c;
                    As[kg + c][i] = (iok && gk < K) ? ap[c] : 0.f;
                }
            }
        } else {
#pragma unroll
            for (int rep = 0; rep < 2; rep++) {
                int t  = tid + rep * 256;
                int k  = t >> 5;
                int ig = (t & 31) * 4;
                int gk = k0 + k;
                const float* ap = A + (long long)gk * lda + i0 + ig;
                bool kok = gk < K;
#pragma unroll
                for (int c = 0; c < 4; c++) {
                    int gi = i0 + ig + c;
                    As[k][ig + c] = (kok && gi < M) ? ap[c] : 0.f;
                }
            }
        }
        // ---- B tile -> Bs[k][j]
        if (BMODE == 0) {
#pragma unroll
            for (int rep = 0; rep < 2; rep++) {
                int t  = tid + rep * 256;
                int j  = t >> 2;
                int kg = (t & 3) * 4;
                int gj = j0 + j;
                const float* bp = B + (long long)gj * ldb + k0 + kg;
                bool jok = gj < N;
#pragma unroll
                for (int c = 0; c < 4; c++) {
                    int gk = k0 + kg + c;
                    Bs[kg + c][j] = (jok && gk < K) ? bp[c] : 0.f;
                }
            }
        } else {
#pragma unroll
            for (int rep = 0; rep < 2; rep++) {
                int t  = tid + rep * 256;
                int k  = t >> 5;
                int jg = (t & 31) * 4;
                int gk = k0 + k;
                const float* bp = B + (long long)gk * ldb + j0 + jg;
                bool kok = gk < K;
#pragma unroll
                for (int c = 0; c < 4; c++) {
                    int gj = j0 + jg + c;
                    Bs[k][jg + c] = (kok && gj < N) ? bp[c] : 0.f;
                }
            }
        }
        __syncthreads();

#pragma unroll
        for (int kk = 0; kk < 16; kk++) {
            float a[8], b[8];
#pragma unroll
            for (int r = 0; r < 8; r++) a[r] = As[kk][ty * 8 + r];
#pragma unroll
            for (int c = 0; c < 8; c++) b[c] = Bs[kk][tx * 8 + c];
#pragma unroll
            for (int r = 0; r < 8; r++)
#pragma unroll
                for (int c = 0; c < 8; c++)
                    acc[r][c] = fmaf(a[r], b[c], acc[r][c]);
        }
        __syncthreads();
    }

    // ---- epilogue
#pragma unroll
    for (int r = 0; r < 8; r++) {
        int gi = i0 + ty * 8 + r;
        if (gi >= M) continue;
#pragma unroll
        for (int c = 0; c < 8; c++) {
            int gj = j0 + tx * 8 + c;
            if (gj >= N) continue;
            float v = acc[r][c] * alpha;
            if (EPI == 2) v += bias[gj];
            if (EPI == 1) {
                // scatter qkv column j=(s,h,d), row i=(b,n) -> g_qkvP[s][b*NH+h][n][d]
                int s  = gj / DIMC;
                int rc = gj - s * DIMC;
                int h  = rc >> 8;
                int d  = rc & 255;
                int b_ = gi / SEQ;
                int n  = gi - b_ * SEQ;
                long long dst = ((((long long)s * BHN) + (b_ * NH + h)) * SEQ + n) * HDIM + d;
                C[dst] = v;
            } else {
                C[(long long)gi * ldc + gj] = v;
            }
        }
    }
}

// ---------------------------------------------------------------------------
// Row softmax stats: per attn row -> max and 1/sum(exp(a-max))
// ---------------------------------------------------------------------------
__global__ void row_stats(const float* __restrict__ attn,
                          float* __restrict__ rmax, float* __restrict__ rinv)
{
    __shared__ float sm[128];
    const long long row = blockIdx.x;
    const float* a = attn + row * SEQ;
    const int t = threadIdx.x;

    float m = -INFINITY;
    for (int i = t; i < SEQ; i += 128) m = fmaxf(m, a[i]);
    sm[t] = m; __syncthreads();
    for (int off = 64; off > 0; off >>= 1) {
        if (t < off) sm[t] = fmaxf(sm[t], sm[t + off]);
        __syncthreads();
    }
    const float M = sm[0]; __syncthreads();

    float s = 0.f;
    for (int i = t; i < SEQ; i += 128) s += __expf(a[i] - M);
    sm[t] = s; __syncthreads();
    for (int off = 64; off > 0; off >>= 1) {
        if (t < off) sm[t] += sm[t + off];
        __syncthreads();
    }
    if (t == 0) { rmax[row] = M; rinv[row] = 1.f / sm[0]; }
}

// ---------------------------------------------------------------------------
// Column softmax stats: online max/sum per column, single pass over attn
// ---------------------------------------------------------------------------
__global__ void col_stats(const float* __restrict__ attn,
                          float* __restrict__ cmax, float* __restrict__ cinv)
{
    const int bh = blockIdx.y;
    const int m  = blockIdx.x * 128 + threadIdx.x;
    const float* a = attn + (long long)bh * SEQ * SEQ + m;

    float mx[4] = {-INFINITY, -INFINITY, -INFINITY, -INFINITY};
    float ss[4] = {0.f, 0.f, 0.f, 0.f};
    for (int n = 0; n < SEQ; n += 4) {
#pragma unroll
        for (int u = 0; u < 4; u++) {
            float v = a[(long long)(n + u) * SEQ];
            if (v <= mx[u]) {
                ss[u] += __expf(v - mx[u]);
            } else {
                ss[u] = ss[u] * __expf(mx[u] - v) + 1.f;
                mx[u] = v;
            }
        }
    }
    float M = fmaxf(fmaxf(mx[0], mx[1]), fmaxf(mx[2], mx[3]));
    float S = 0.f;
#pragma unroll
    for (int u = 0; u < 4; u++) S += ss[u] * __expf(mx[u] - M);
    cmax[bh * SEQ + m] = M;
    cinv[bh * SEQ + m] = 1.f / S;
}

// ---------------------------------------------------------------------------
// attn_f = softmax_row(a) * softmax_col(a) = exp(2a - rmax - cmax)*rinv*cinv
// ---------------------------------------------------------------------------
__global__ void apply_softmax(float4* __restrict__ attn,
                              const float* __restrict__ rmax, const float* __restrict__ rinv,
                              const float* __restrict__ cmax, const float* __restrict__ cinv)
{
    const long long id = (long long)blockIdx.x * blockDim.x + threadIdx.x;  // float4 index
    if (id >= (long long)BHN * SEQ * SEQ / 4) return;
    const long long base = id * 4;
    const int m0 = (int)(base % SEQ);
    const long long rg = base / SEQ;          // global row (bh*SEQ + n)
    const int bh = (int)(rg / SEQ);

    const float rm = rmax[rg];
    const float ri = rinv[rg];
    const float4 cm = *(const float4*)(cmax + (long long)bh * SEQ + m0);
    const float4 ci = *(const float4*)(cinv + (long long)bh * SEQ + m0);

    float4 v = attn[id];
    v.x = __expf(2.f * v.x - rm - cm.x) * ri * ci.x;
    v.y = __expf(2.f * v.y - rm - cm.y) * ri * ci.y;
    v.z = __expf(2.f * v.z - rm - cm.z) * ri * ci.z;
    v.w = __expf(2.f * v.w - rm - cm.w) * ri * ci.w;
    attn[id] = v;
}

// ---------------------------------------------------------------------------
// v_cat[bh][n][0:256] = v ; [256:262] = (y^2, x^2, xy, y, x, 1)
// ---------------------------------------------------------------------------
__global__ void build_vcat(const float* __restrict__ qkvP, float* __restrict__ vcat)
{
    const int rid = blockIdx.x;          // bh*SEQ + n
    const int bh  = rid / SEQ;
    const int n   = rid - bh * SEQ;
    const float* src = qkvP + ((long long)(2 * BHN + bh) * SEQ + n) * HDIM;
    float* dst = vcat + (long long)rid * DD;
    const int t = threadIdx.x;
    dst[t] = src[t];
    if (t < 6) {
        int iy = n % 48;
        int ix = n / 48;
        float y = -1.f + 2.f * (float)iy / 47.f;
        float x = -1.f + 2.f * (float)ix / 63.f;
        float p = (t == 0) ? y * y :
                  (t == 1) ? x * x :
                  (t == 2) ? y * x :
                  (t == 3) ? y :
                  (t == 4) ? x : 1.f;
        dst[HDIM + t] = p;
    }
}

// ---------------------------------------------------------------------------
// fundT[b][e][h*DD+d] = fund[bh][d][e]   (reshape + transpose(0,2,1))
// ---------------------------------------------------------------------------
__global__ void transpose_fund(const float* __restrict__ fund, float* __restrict__ fundT)
{
    const long long idx = (long long)blockIdx.x * blockDim.x + threadIdx.x;
    if (idx >= (long long)BHN * DD * DD) return;
    const int e  = (int)(idx % DD);
    const long long r = idx / DD;
    const int d  = (int)(r % DD);
    const int bh = (int)(r / DD);
    const int b  = bh / NH;
    const int h  = bh - b * NH;
    fundT[((long long)b * DD + e) * HD3 + h * DD + d] = fund[idx];
}

// ---------------------------------------------------------------------------
// Launch
// ---------------------------------------------------------------------------
extern "C" void kernel_launch(void* const* d_in, const int* in_sizes, int n_in,
                              void* d_out, int out_size)
{
    const float* x    = (const float*)d_in[0];  // [4,3072,768]
    const float* Wqkv = (const float*)d_in[1];  // [2304,768]
    const float* Wpf  = (const float*)d_in[2];  // [768,786]
    const float* bpf  = (const float*)d_in[3];  // [768]
    float* out = (float*)d_out;                 // [4,262,768]

    float *qkvP, *attn, *vcat, *f1, *fund, *fundT, *rmax, *rinv, *cmax, *cinv;
    cudaGetSymbolAddress((void**)&qkvP,  g_qkvP);
    cudaGetSymbolAddress((void**)&attn,  g_attn);
    cudaGetSymbolAddress((void**)&vcat,  g_vcat);
    cudaGetSymbolAddress((void**)&f1,    g_f1);
    cudaGetSymbolAddress((void**)&fund,  g_fund);
    cudaGetSymbolAddress((void**)&fundT, g_fundT);
    cudaGetSymbolAddress((void**)&rmax,  g_rmax);
    cudaGetSymbolAddress((void**)&rinv,  g_rinv);
    cudaGetSymbolAddress((void**)&cmax,  g_cmax);
    cudaGetSymbolAddress((void**)&cinv,  g_cinv);

    const long long sQ = (long long)SEQ * HDIM;

    // 1) QKV projection, scattered to [s][bh][n][d]
    gemm_k<0, 0, 1><<<dim3((3 * DIMC) / 128, (BB * SEQ) / 128, 1), 256>>>(
        x, Wqkv, qkvP, nullptr,
        BB * SEQ, 3 * DIMC, DIMC, DIMC, DIMC, 0, 0, 0, 0, 1.f);

    // 2) attn = scale * q @ k^T   (batched over bh)
    gemm_k<0, 0, 0><<<dim3(SEQ / 128, SEQ / 128, BHN), 256>>>(
        qkvP, qkvP + (long long)BHN * sQ, attn, nullptr,
        SEQ, SEQ, HDIM, HDIM, HDIM, SEQ,
        sQ, sQ, (long long)SEQ * SEQ, 0.0625f);

    // 3) softmax stats
    row_stats<<<BHN * SEQ, 128>>>(attn, rmax, rinv);
    col_stats<<<dim3(SEQ / 128, BHN), 128>>>(attn, cmax, cinv);

    // 4) attn_f in place
    apply_softmax<<<(unsigned)(((long long)BHN * SEQ * SEQ / 4 + 255) / 256), 256>>>(
        (float4*)attn, rmax, rinv, cmax, cinv);

    // 5) v_cat = [v, pos]
    build_vcat<<<BHN * SEQ, 256>>>(qkvP, vcat);

    // 6) f1[d,m] = sum_n v_cat[n,d] * attn_f[n,m]
    gemm_k<1, 1, 0><<<dim3(SEQ / 128, (DD + 127) / 128, BHN), 256>>>(
        vcat, attn, f1, nullptr,
        DD, SEQ, SEQ, DD, SEQ, SEQ,
        (long long)SEQ * DD, (long long)SEQ * SEQ, (long long)DD * SEQ, 1.f);

    // 7) fund[d,e] = sum_m f1[d,m] * v_cat[m,e]
    gemm_k<0, 1, 0><<<dim3((DD + 127) / 128, (DD + 127) / 128, BHN), 256>>>(
        f1, vcat, fund, nullptr,
        DD, DD, SEQ, SEQ, DD, DD,
        (long long)DD * SEQ, (long long)SEQ * DD, (long long)DD * DD, 1.f);

    // 8) reshape/transpose
    transpose_fund<<<(int)(((long long)BHN * DD * DD + 255) / 256), 256>>>(fund, fundT);

    // 9) out[b,e,o] = sum_j fundT[b,e,j] * Wpf[o,j] + bpf[o]
    gemm_k<0, 0, 2><<<dim3(DIMC / 128, (DD + 127) / 128, BB), 256>>>(
        fundT, Wpf, out, bpf,
        DD, DIMC, HD3, HD3, HD3, DIMC,
        (long long)DD * HD3, 0, (long long)DD * DIMC, 1.f);
}